// round 4
// baseline (speedup 1.0000x reference)
#include <cuda_runtime.h>
#include <cuda_bf16.h>
#include <cstdint>
#include <cstring>

// Problem: N=8,S=2048 -> T=16384 tokens, D=O=2048, E=8, top-2
#define T_TOKENS 16384
#define DIM_D    2048
#define DIM_O    2048
#define N_EXP    8
#define MAX_TILES 264               // ceil-per-expert padding worst case
#define R_MAX    (MAX_TILES * 128)  // padded rows

#define BM 128
#define BN 64
#define BK 32
#define QMAX 32639.0f               // 127*256+127

// ---------------- device scratch (static; no allocation) ----------------
__device__ float g_operm[(size_t)R_MAX * DIM_O];           // relu(XW+b) rows
__device__ signed char g_xqh[(size_t)T_TOKENS * DIM_D];    // x hi int8 (token order)
__device__ signed char g_xql[(size_t)T_TOKENS * DIM_D];    // x lo int8
__device__ signed char g_wqh[(size_t)N_EXP * DIM_O * DIM_D]; // W^T hi [e][o][d]
__device__ signed char g_wql[(size_t)N_EXP * DIM_O * DIM_D]; // W^T lo
__device__ unsigned g_amax_x, g_amax_w;
__device__ int g_top[T_TOKENS * 2];
__device__ int g_counts[N_EXP];
__device__ int g_offsets[N_EXP];
__device__ int g_cursor[N_EXP];
__device__ int g_rows[R_MAX];        // padded row -> token (-1 pad)
__device__ int g_pos[T_TOKENS * 2];  // (token,k) -> padded row
__device__ int g_tile_e[MAX_TILES];
__device__ int g_tile_r0[MAX_TILES];
__device__ int g_num_tiles;
__device__ int g_total_rows;

// ---------------- helpers ----------------
__device__ __forceinline__ uint32_t smem_u32(const void* p) {
    uint32_t a;
    asm("{ .reg .u64 t; cvta.to.shared.u64 t, %1; cvt.u32.u64 %0, t; }" : "=r"(a) : "l"(p));
    return a;
}
__device__ __forceinline__ void cp16(uint32_t dst, const void* src, int nbytes) {
    asm volatile("cp.async.ca.shared.global [%0], [%1], 16, %2;"
                 :: "r"(dst), "l"(src), "r"(nbytes) : "memory");
}
#define CP_COMMIT() asm volatile("cp.async.commit_group;" ::: "memory")
#define CP_WAIT1()  asm volatile("cp.async.wait_group 1;" ::: "memory")
__device__ __forceinline__ void imma(int* d, const uint32_t* a, uint32_t b0, uint32_t b1) {
    asm volatile(
        "mma.sync.aligned.m16n8k32.row.col.s32.s8.s8.s32 "
        "{%0,%1,%2,%3}, {%4,%5,%6,%7}, {%8,%9}, {%0,%1,%2,%3};"
        : "+r"(d[0]), "+r"(d[1]), "+r"(d[2]), "+r"(d[3])
        : "r"(a[0]), "r"(a[1]), "r"(a[2]), "r"(a[3]), "r"(b0), "r"(b1));
}

// ---------------- init ----------------
__global__ void init_k() {
    int i = threadIdx.x;
    if (i < N_EXP) { g_counts[i] = 0; g_cursor[i] = 0; }
    if (i == 0) { g_amax_x = 0u; g_amax_w = 0u; }
}

// ---------------- absmax reduction ----------------
__global__ void absmax_k(const float* __restrict__ p, int n4, unsigned* dst) {
    __shared__ float sm[8];
    int tid = threadIdx.x;
    float m = 0.f;
    for (int i = blockIdx.x * blockDim.x + tid; i < n4; i += gridDim.x * blockDim.x) {
        float4 v = ((const float4*)p)[i];
        m = fmaxf(m, fmaxf(fmaxf(fabsf(v.x), fabsf(v.y)), fmaxf(fabsf(v.z), fabsf(v.w))));
    }
#pragma unroll
    for (int off = 16; off; off >>= 1) m = fmaxf(m, __shfl_xor_sync(0xffffffffu, m, off));
    if ((tid & 31) == 0) sm[tid >> 5] = m;
    __syncthreads();
    if (tid < 8) {
        m = sm[tid];
#pragma unroll
        for (int off = 4; off; off >>= 1) m = fmaxf(m, __shfl_xor_sync(0xffu, m, off));
        if (tid == 0) atomicMax(dst, __float_as_uint(m));
    }
}

// ---------------- gate: fp32 logits + top-2 (warp per token) ----------------
__global__ void gate_k(const float* __restrict__ x,
                       const float* __restrict__ gw,
                       const float* __restrict__ gb) {
    int warp = (blockIdx.x * blockDim.x + threadIdx.x) >> 5;
    int lane = threadIdx.x & 31;
    if (warp >= T_TOKENS) return;
    const float* xr = x + (size_t)warp * DIM_D;
    float acc[N_EXP];
#pragma unroll
    for (int e = 0; e < N_EXP; e++) acc[e] = 0.f;
    for (int k = lane; k < DIM_D; k += 32) {
        float xv = xr[k];
        const float4* g4 = (const float4*)(gw + (size_t)k * N_EXP);
        float4 a = g4[0], b = g4[1];
        acc[0] += xv * a.x; acc[1] += xv * a.y; acc[2] += xv * a.z; acc[3] += xv * a.w;
        acc[4] += xv * b.x; acc[5] += xv * b.y; acc[6] += xv * b.z; acc[7] += xv * b.w;
    }
#pragma unroll
    for (int e = 0; e < N_EXP; e++)
#pragma unroll
        for (int off = 16; off; off >>= 1)
            acc[e] += __shfl_xor_sync(0xffffffffu, acc[e], off);
    if (lane == 0) {
        float v1 = -1e30f, v2 = -1e30f; int i1 = 0, i2 = 0;
#pragma unroll
        for (int e = 0; e < N_EXP; e++) {
            float v = acc[e] + gb[e];
            if (v > v1)      { v2 = v1; i2 = i1; v1 = v; i1 = e; }
            else if (v > v2) { v2 = v;  i2 = e; }
        }
        g_top[warp * 2 + 0] = i1;
        g_top[warp * 2 + 1] = i2;
        atomicAdd(&g_counts[i1], 1);
        atomicAdd(&g_counts[i2], 1);
    }
}

// ---------------- scan: padded offsets + tile table ----------------
__global__ void scan_k() {
    if (threadIdx.x != 0) return;
    int o = 0, t = 0;
    for (int e = 0; e < N_EXP; e++) {
        g_offsets[e] = o;
        int nt = (g_counts[e] + 127) / 128;
        for (int i = 0; i < nt; i++) { g_tile_e[t] = e; g_tile_r0[t] = o + i * 128; t++; }
        o += nt * 128;
    }
    g_num_tiles = t;
    g_total_rows = o;
}

// ---------------- scatter ----------------
__global__ void scatter_k() {
    int i = blockIdx.x * blockDim.x + threadIdx.x;
    if (i >= T_TOKENS * 2) return;
    int e = g_top[i];
    int pos = atomicAdd(&g_cursor[e], 1);
    int row = g_offsets[e] + pos;
    g_rows[row] = i >> 1;
    g_pos[i] = row;
}

// ---------------- quantize x (token order): hi/lo int8 split ----------------
__global__ void quant_x_k(const float* __restrict__ x) {
    size_t i = ((size_t)blockIdx.x * blockDim.x + threadIdx.x) * 4;
    float inv = QMAX / __uint_as_float(g_amax_x);
    float4 v = *(const float4*)(x + i);
    int q0 = __float2int_rn(v.x * inv), q1 = __float2int_rn(v.y * inv);
    int q2 = __float2int_rn(v.z * inv), q3 = __float2int_rn(v.w * inv);
    int h0 = (q0 + 128) >> 8, h1 = (q1 + 128) >> 8, h2 = (q2 + 128) >> 8, h3 = (q3 + 128) >> 8;
    int l0 = q0 - (h0 << 8), l1 = q1 - (h1 << 8), l2 = q2 - (h2 << 8), l3 = q3 - (h3 << 8);
    unsigned hp = (h0 & 255) | ((h1 & 255) << 8) | ((h2 & 255) << 16) | ((unsigned)(h3 & 255) << 24);
    unsigned lp = (l0 & 255) | ((l1 & 255) << 8) | ((l2 & 255) << 16) | ((unsigned)(l3 & 255) << 24);
    *(unsigned*)(g_xqh + i) = hp;
    *(unsigned*)(g_xql + i) = lp;
}

// ---------------- quantize + transpose W[e][d][o] -> Wt[e][o][d] ----------------
__global__ void quant_w_k(const float* __restrict__ w) {
    __shared__ float tf[64][65];
    int e = blockIdx.z;
    int d0 = blockIdx.x * 64, o0 = blockIdx.y * 64;
    const float* we = w + ((size_t)e * DIM_D + d0) * DIM_O + o0;
    int dd = threadIdx.x >> 2, oq = (threadIdx.x & 3) * 16;
#pragma unroll
    for (int c = 0; c < 4; c++) {
        float4 v = *(const float4*)(we + (size_t)dd * DIM_O + oq + 4 * c);
        tf[dd][oq + 4 * c + 0] = v.x; tf[dd][oq + 4 * c + 1] = v.y;
        tf[dd][oq + 4 * c + 2] = v.z; tf[dd][oq + 4 * c + 3] = v.w;
    }
    __syncthreads();
    float inv = QMAX / __uint_as_float(g_amax_w);
    int oo = threadIdx.x >> 2, dq = (threadIdx.x & 3) * 16;
    union { signed char c[16]; int4 v; } hu, lu;
#pragma unroll
    for (int j = 0; j < 16; j++) {
        int qv = __float2int_rn(tf[dq + j][oo] * inv);
        int h = (qv + 128) >> 8;
        hu.c[j] = (signed char)h;
        lu.c[j] = (signed char)(qv - (h << 8));
    }
    size_t off = ((size_t)e * DIM_O + o0 + oo) * DIM_D + d0 + dq;
    *(int4*)(g_wqh + off) = hu.v;
    *(int4*)(g_wql + off) = lu.v;
}

// ---------------- grouped GEMM via split-int8 IMMA ----------------
// per-thread result = sx*sw*(65536*hh + 256*cross); lo*lo dropped (~5e-5 rel)
__global__ void __launch_bounds__(256, 2)
moe_imma(const float* __restrict__ eb) {
    int mt = blockIdx.y;
    if (mt >= g_num_tiles) return;
    int e    = g_tile_e[mt];
    int row0 = g_tile_r0[mt];
    int n0   = blockIdx.x * BN;

    __shared__ __align__(16) signed char Ah[2][BM][48];
    __shared__ __align__(16) signed char Al[2][BM][48];
    __shared__ __align__(16) signed char Bh[2][BN][48];
    __shared__ __align__(16) signed char Bl[2][BN][48];

    int tid = threadIdx.x;

    // producers: A rows (256 thr = 128 rows x 2 chunks), B rows (128 thr per fmt)
    int prow = tid >> 1;
    int pch  = (tid & 1) * 16;
    int tok  = g_rows[row0 + prow];
    const signed char* ah_src = g_xqh + ((size_t)(tok < 0 ? 0 : tok) << 11) + pch;
    const signed char* al_src = g_xql + ((size_t)(tok < 0 ? 0 : tok) << 11) + pch;
    int apred = (tok >= 0) ? 16 : 0;
    int brow = (tid & 127) >> 1;
    const signed char* b_src = ((tid < 128) ? g_wqh : g_wql)
        + ((size_t)e * DIM_O + n0 + brow) * DIM_D + pch;
    uint32_t ah_dst[2], al_dst[2], b_dst[2];
#pragma unroll
    for (int s = 0; s < 2; s++) {
        ah_dst[s] = smem_u32(&Ah[s][prow][pch]);
        al_dst[s] = smem_u32(&Al[s][prow][pch]);
        b_dst[s]  = (tid < 128) ? smem_u32(&Bh[s][brow][pch]) : smem_u32(&Bl[s][brow][pch]);
    }

    int warp = tid >> 5, lane = tid & 31;
    int g = lane >> 2, q = lane & 3;
    int wm = (warp & 3) * 32;   // warp rows (4 M-warps)
    int wn = (warp >> 2) * 32;  // warp cols (2 N-warps)

    int hh[2][4][4], cr[2][4][4];
#pragma unroll
    for (int t = 0; t < 2; t++)
#pragma unroll
        for (int n = 0; n < 4; n++)
#pragma unroll
            for (int j = 0; j < 4; j++) { hh[t][n][j] = 0; cr[t][n][j] = 0; }

    // prologue: stage 0
    cp16(ah_dst[0], ah_src, apred);
    cp16(al_dst[0], al_src, apred);
    cp16(b_dst[0],  b_src,  16);
    CP_COMMIT();

    const int KSTEPS = DIM_D / BK;  // 64
    for (int ks = 0; ks < KSTEPS; ks++) {
        int s = ks & 1;
        if (ks + 1 < KSTEPS) {
            int k0 = (ks + 1) * BK;
            cp16(ah_dst[s ^ 1], ah_src + k0, apred);
            cp16(al_dst[s ^ 1], al_src + k0, apred);
            cp16(b_dst[s ^ 1],  b_src + k0,  16);
        }
        CP_COMMIT();
        CP_WAIT1();
        __syncthreads();

        uint32_t a_h[2][4], a_l[2][4];
#pragma unroll
        for (int t = 0; t < 2; t++) {
            int r = wm + 16 * t + g;
            a_h[t][0] = *(const uint32_t*)&Ah[s][r][4 * q];
            a_h[t][1] = *(const uint32_t*)&Ah[s][r + 8][4 * q];
            a_h[t][2] = *(const uint32_t*)&Ah[s][r][16 + 4 * q];
            a_h[t][3] = *(const uint32_t*)&Ah[s][r + 8][16 + 4 * q];
            a_l[t][0] = *(const uint32_t*)&Al[s][r][4 * q];
            a_l[t][1] = *(const uint32_t*)&Al[s][r + 8][4 * q];
            a_l[t][2] = *(const uint32_t*)&Al[s][r][16 + 4 * q];
            a_l[t][3] = *(const uint32_t*)&Al[s][r + 8][16 + 4 * q];
        }
#pragma unroll
        for (int nt = 0; nt < 4; nt++) {
            int bn = wn + 8 * nt + g;
            uint32_t bh0 = *(const uint32_t*)&Bh[s][bn][4 * q];
            uint32_t bh1 = *(const uint32_t*)&Bh[s][bn][16 + 4 * q];
            uint32_t bl0 = *(const uint32_t*)&Bl[s][bn][4 * q];
            uint32_t bl1 = *(const uint32_t*)&Bl[s][bn][16 + 4 * q];
#pragma unroll
            for (int t = 0; t < 2; t++) {
                imma(hh[t][nt], a_h[t], bh0, bh1);
                imma(cr[t][nt], a_h[t], bl0, bl1);
                imma(cr[t][nt], a_l[t], bh0, bh1);
            }
        }
        __syncthreads();
    }

    // epilogue: dequant + bias + relu -> g_operm
    float sc = (__uint_as_float(g_amax_x) / QMAX) * (__uint_as_float(g_amax_w) / QMAX);
    const float* ebrow = eb + (size_t)e * DIM_O;
#pragma unroll
    for (int t = 0; t < 2; t++) {
#pragma unroll
        for (int nt = 0; nt < 4; nt++) {
            int col = n0 + wn + 8 * nt + 2 * q;
            float b0v = ebrow[col], b1v = ebrow[col + 1];
            int r = row0 + wm + 16 * t + g;
            float v0 = 65536.f * (float)hh[t][nt][0] + 256.f * (float)cr[t][nt][0];
            float v1 = 65536.f * (float)hh[t][nt][1] + 256.f * (float)cr[t][nt][1];
            float v2 = 65536.f * (float)hh[t][nt][2] + 256.f * (float)cr[t][nt][2];
            float v3 = 65536.f * (float)hh[t][nt][3] + 256.f * (float)cr[t][nt][3];
            float2 o0, o1;
            o0.x = fmaxf(fmaf(v0, sc, b0v), 0.f);
            o0.y = fmaxf(fmaf(v1, sc, b1v), 0.f);
            o1.x = fmaxf(fmaf(v2, sc, b0v), 0.f);
            o1.y = fmaxf(fmaf(v3, sc, b1v), 0.f);
            *(float2*)(g_operm + (size_t)r * DIM_O + col) = o0;
            *(float2*)(g_operm + (size_t)(r + 8) * DIM_O + col) = o1;
        }
    }
}

// ---------------- combine: out[t] = 0.5*(row_e1 + row_e2) ----------------
__global__ void combine_k(float* __restrict__ out) {
    int t = blockIdx.x;
    const float4* a = (const float4*)(g_operm + (size_t)g_pos[2 * t] * DIM_O);
    const float4* b = (const float4*)(g_operm + (size_t)g_pos[2 * t + 1] * DIM_O);
    float4* o = (float4*)(out + (size_t)t * DIM_O);
    for (int i = threadIdx.x; i < DIM_O / 4; i += blockDim.x) {
        float4 va = a[i], vb = b[i];
        float4 v;
        v.x = 0.5f * (va.x + vb.x); v.y = 0.5f * (va.y + vb.y);
        v.z = 0.5f * (va.z + vb.z); v.w = 0.5f * (va.w + vb.w);
        o[i] = v;
    }
}

// ---------------- host ----------------
extern "C" void kernel_launch(void* const* d_in, const int* in_sizes, int n_in,
                              void* d_out, int out_size) {
    const float* x  = (const float*)d_in[0];
    const float* gw = (const float*)d_in[1];
    const float* gb = (const float*)d_in[2];
    const float* ew = (const float*)d_in[3];
    const float* eb = (const float*)d_in[4];
    float* out = (float*)d_out;

    void *p_rows, *p_ax, *p_aw;
    cudaGetSymbolAddress(&p_rows, g_rows);
    cudaGetSymbolAddress(&p_ax, g_amax_x);
    cudaGetSymbolAddress(&p_aw, g_amax_w);

    init_k<<<1, 32>>>();
    cudaMemsetAsync(p_rows, 0xFF, R_MAX * sizeof(int));
    absmax_k<<<1024, 256>>>(x, T_TOKENS * DIM_D / 4, (unsigned*)p_ax);
    absmax_k<<<1024, 256>>>(ew, N_EXP * DIM_D * DIM_O / 4, (unsigned*)p_aw);
    gate_k<<<T_TOKENS / 8, 256>>>(x, gw, gb);
    scan_k<<<1, 1>>>();
    scatter_k<<<(T_TOKENS * 2) / 256, 256>>>();
    quant_x_k<<<T_TOKENS * DIM_D / 1024, 256>>>(x);
    quant_w_k<<<dim3(DIM_D / 64, DIM_O / 64, N_EXP), 256>>>(ew);
    moe_imma<<<dim3(DIM_O / BN, MAX_TILES), 256>>>(eb);
    combine_k<<<T_TOKENS, 256>>>(out);
}

// round 5
// speedup vs baseline: 4.0002x; 4.0002x over previous
#include <cuda_runtime.h>
#include <cuda_fp16.h>
#include <cstdint>

// Problem: N=8,S=2048 -> T=16384 tokens, D=O=2048, E=8, top-2
#define T_TOKENS 16384
#define DIM_D    2048
#define DIM_O    2048
#define N_EXP    8
#define MAX_TILES 264               // ceil-per-expert padding worst case
#define R_MAX    (MAX_TILES * 128)  // padded rows

#define BM 128
#define BN 128
#define BK 32
#define ROWB 160                    // smem row stride bytes (data 64B + pad)

// ---------------- device scratch (static; no allocation) ----------------
__device__ float g_operm[(size_t)R_MAX * DIM_O];            // relu(XW+b) rows
__device__ __half g_xh[(size_t)T_TOKENS * DIM_D];           // x fp16 (token order)
__device__ __half g_wt[(size_t)N_EXP * DIM_O * DIM_D];      // W^T fp16 [e][o][d]
__device__ int g_top[T_TOKENS * 2];
__device__ int g_counts[N_EXP];
__device__ int g_offsets[N_EXP];
__device__ int g_cursor[N_EXP];
__device__ int g_rows[R_MAX];        // padded row -> token (-1 pad)
__device__ int g_pos[T_TOKENS * 2];  // (token,k) -> padded row
__device__ int g_tile_e[MAX_TILES];
__device__ int g_tile_r0[MAX_TILES];
__device__ int g_num_tiles;
__device__ int g_total_rows;

__device__ __forceinline__ void mma_f16(float* d, uint32_t a0, uint32_t a1, uint32_t a2,
                                        uint32_t a3, uint32_t b0, uint32_t b1) {
    asm volatile(
        "mma.sync.aligned.m16n8k16.row.col.f32.f16.f16.f32 "
        "{%0,%1,%2,%3}, {%4,%5,%6,%7}, {%8,%9}, {%0,%1,%2,%3};"
        : "+f"(d[0]), "+f"(d[1]), "+f"(d[2]), "+f"(d[3])
        : "r"(a0), "r"(a1), "r"(a2), "r"(a3), "r"(b0), "r"(b1));
}

// ---------------- init ----------------
__global__ void init_k() {
    int i = threadIdx.x;
    if (i < N_EXP) { g_counts[i] = 0; g_cursor[i] = 0; }
}

// ---------------- gate: fp32 logits + top-2 (warp per token) ----------------
__global__ void gate_k(const float* __restrict__ x,
                       const float* __restrict__ gw,
                       const float* __restrict__ gb) {
    int warp = (blockIdx.x * blockDim.x + threadIdx.x) >> 5;
    int lane = threadIdx.x & 31;
    if (warp >= T_TOKENS) return;
    const float* xr = x + (size_t)warp * DIM_D;
    float acc[N_EXP];
#pragma unroll
    for (int e = 0; e < N_EXP; e++) acc[e] = 0.f;
    for (int k = lane; k < DIM_D; k += 32) {
        float xv = xr[k];
        const float4* g4 = (const float4*)(gw + (size_t)k * N_EXP);
        float4 a = g4[0], b = g4[1];
        acc[0] += xv * a.x; acc[1] += xv * a.y; acc[2] += xv * a.z; acc[3] += xv * a.w;
        acc[4] += xv * b.x; acc[5] += xv * b.y; acc[6] += xv * b.z; acc[7] += xv * b.w;
    }
#pragma unroll
    for (int e = 0; e < N_EXP; e++)
#pragma unroll
        for (int off = 16; off; off >>= 1)
            acc[e] += __shfl_xor_sync(0xffffffffu, acc[e], off);
    if (lane == 0) {
        float v1 = -1e30f, v2 = -1e30f; int i1 = 0, i2 = 0;
#pragma unroll
        for (int e = 0; e < N_EXP; e++) {
            float v = acc[e] + gb[e];
            if (v > v1)      { v2 = v1; i2 = i1; v1 = v; i1 = e; }
            else if (v > v2) { v2 = v;  i2 = e; }
        }
        g_top[warp * 2 + 0] = i1;
        g_top[warp * 2 + 1] = i2;
        atomicAdd(&g_counts[i1], 1);
        atomicAdd(&g_counts[i2], 1);
    }
}

// ---------------- scan: padded offsets + tile table ----------------
__global__ void scan_k() {
    if (threadIdx.x != 0) return;
    int o = 0, t = 0;
    for (int e = 0; e < N_EXP; e++) {
        g_offsets[e] = o;
        int nt = (g_counts[e] + 127) / 128;
        for (int i = 0; i < nt; i++) { g_tile_e[t] = e; g_tile_r0[t] = o + i * 128; t++; }
        o += nt * 128;
    }
    g_num_tiles = t;
    g_total_rows = o;
}

// ---------------- scatter ----------------
__global__ void scatter_k() {
    int i = blockIdx.x * blockDim.x + threadIdx.x;
    if (i >= T_TOKENS * 2) return;
    int e = g_top[i];
    int pos = atomicAdd(&g_cursor[e], 1);
    int row = g_offsets[e] + pos;
    g_rows[row] = i >> 1;
    g_pos[i] = row;
}

// ---------------- convert x -> fp16 (token order) ----------------
__global__ void xh_k(const float* __restrict__ x) {
    size_t i = ((size_t)blockIdx.x * blockDim.x + threadIdx.x) * 8;
    float4 v0 = *(const float4*)(x + i);
    float4 v1 = *(const float4*)(x + i + 4);
    union { __half2 h[4]; uint4 u; } o;
    o.h[0] = __floats2half2_rn(v0.x, v0.y);
    o.h[1] = __floats2half2_rn(v0.z, v0.w);
    o.h[2] = __floats2half2_rn(v1.x, v1.y);
    o.h[3] = __floats2half2_rn(v1.z, v1.w);
    *(uint4*)(g_xh + i) = o.u;
}

// ---------------- transpose+convert W[e][d][o] -> Wt[e][o][d] fp16 ----------------
__global__ void wt_k(const float* __restrict__ w) {
    __shared__ float tf[64][65];
    int e = blockIdx.z;
    int d0 = blockIdx.x * 64, o0 = blockIdx.y * 64;
    const float* we = w + ((size_t)e * DIM_D + d0) * DIM_O + o0;
    int dd = threadIdx.x >> 2, oq = (threadIdx.x & 3) * 16;
#pragma unroll
    for (int c = 0; c < 4; c++) {
        float4 v = *(const float4*)(we + (size_t)dd * DIM_O + oq + 4 * c);
        tf[dd][oq + 4 * c + 0] = v.x; tf[dd][oq + 4 * c + 1] = v.y;
        tf[dd][oq + 4 * c + 2] = v.z; tf[dd][oq + 4 * c + 3] = v.w;
    }
    __syncthreads();
    int oo = threadIdx.x >> 2, dq = (threadIdx.x & 3) * 16;
    union { __half2 h[8]; uint4 u[2]; } ou;
#pragma unroll
    for (int j = 0; j < 8; j++)
        ou.h[j] = __floats2half2_rn(tf[dq + 2 * j][oo], tf[dq + 2 * j + 1][oo]);
    size_t off = ((size_t)e * DIM_O + o0 + oo) * DIM_D + d0 + dq;
    *(uint4*)(g_wt + off) = ou.u[0];
    *(uint4*)(g_wt + off + 8) = ou.u[1];
}

// ---------------- grouped GEMM via fp16 mma.sync (fp32 accum) ----------------
__global__ void __launch_bounds__(256, 2)
moe_hmma(const float* __restrict__ eb) {
    int mt = blockIdx.y;
    if (mt >= g_num_tiles) return;
    int e    = g_tile_e[mt];
    int row0 = g_tile_r0[mt];
    int n0   = blockIdx.x * BN;

    // rows: 64 data bytes (32 halves) + pad to 160B stride.
    // within-row layout per k16 block (32B): pairs [2q,2q+1] at byte 8q,
    // [2q+8,2q+9] at byte 8q+4  -> every fragment is one aligned LDS.64.
    __shared__ __align__(16) char As[BM * ROWB];
    __shared__ __align__(16) char Bs[BN * ROWB];
    __shared__ int toks[BM];

    int tid = threadIdx.x;
    if (tid < BM) toks[tid] = g_rows[row0 + tid];
    __syncthreads();

    // loader mapping: thread t -> row t>>1, k16-block t&1 (16 halves = 32B)
    int lrow  = tid >> 1;
    int lpart = tid & 1;
    int tok   = toks[lrow];
    const __half* a_src = g_xh + ((size_t)(tok < 0 ? 0 : tok) << 11) + 16 * lpart;
    const __half* b_src = g_wt + ((size_t)e * DIM_O + n0 + lrow) * DIM_D + 16 * lpart;
    char* a_dst = As + lrow * ROWB + 32 * lpart;
    char* b_dst = Bs + lrow * ROWB + 32 * lpart;

    // warp / fragment mapping
    int warp = tid >> 5, lane = tid & 31;
    int wm = (warp & 3) * 32;    // 4 M-warps x 2 m16 tiles
    int wn = (warp >> 2) * 64;   // 2 N-warps x 8 n8 tiles
    int g = lane >> 2, q = lane & 3;

    float acc[2][8][4];
#pragma unroll
    for (int t = 0; t < 2; t++)
#pragma unroll
        for (int n = 0; n < 8; n++)
#pragma unroll
            for (int j = 0; j < 4; j++) acc[t][n][j] = 0.f;

    const uint4 z4 = make_uint4(0, 0, 0, 0);
    uint4 aR0, aR1, bR0, bR1;   // halves [0..7], [8..15] of this thread's 16-half part

    aR0 = (tok >= 0) ? *(const uint4*)a_src : z4;
    aR1 = (tok >= 0) ? *(const uint4*)(a_src + 8) : z4;
    bR0 = *(const uint4*)b_src;
    bR1 = *(const uint4*)(b_src + 8);

    for (int k0 = 0; k0 < DIM_D; k0 += BK) {
        __syncthreads();  // previous compute done before overwrite
        // interleaved store: {lower pair j, upper pair j} as one 8B word at byte 8j
        ((uint2*)a_dst)[0] = make_uint2(aR0.x, aR1.x);
        ((uint2*)a_dst)[1] = make_uint2(aR0.y, aR1.y);
        ((uint2*)a_dst)[2] = make_uint2(aR0.z, aR1.z);
        ((uint2*)a_dst)[3] = make_uint2(aR0.w, aR1.w);
        ((uint2*)b_dst)[0] = make_uint2(bR0.x, bR1.x);
        ((uint2*)b_dst)[1] = make_uint2(bR0.y, bR1.y);
        ((uint2*)b_dst)[2] = make_uint2(bR0.z, bR1.z);
        ((uint2*)b_dst)[3] = make_uint2(bR0.w, bR1.w);
        __syncthreads();

        int kn = k0 + BK;
        if (kn < DIM_D) {   // prefetch next slab
            aR0 = (tok >= 0) ? *(const uint4*)(a_src + kn) : z4;
            aR1 = (tok >= 0) ? *(const uint4*)(a_src + kn + 8) : z4;
            bR0 = *(const uint4*)(b_src + kn);
            bR1 = *(const uint4*)(b_src + kn + 8);
        }

#pragma unroll
        for (int cb = 0; cb < 2; cb++) {
            int boff = 32 * cb + 8 * q;
            uint2 aa[2], ab[2];
#pragma unroll
            for (int t = 0; t < 2; t++) {
                int r = wm + 16 * t + g;
                aa[t] = *(const uint2*)(As + r * ROWB + boff);        // a0, a2
                ab[t] = *(const uint2*)(As + (r + 8) * ROWB + boff);  // a1, a3
            }
#pragma unroll
            for (int nt = 0; nt < 8; nt++) {
                int n = wn + 8 * nt + g;
                uint2 bb = *(const uint2*)(Bs + n * ROWB + boff);     // b0, b1
                mma_f16(acc[0][nt], aa[0].x, ab[0].x, aa[0].y, ab[0].y, bb.x, bb.y);
                mma_f16(acc[1][nt], aa[1].x, ab[1].x, aa[1].y, ab[1].y, bb.x, bb.y);
            }
        }
    }

    // epilogue: relu(acc + bias) -> g_operm
    const float* ebrow = eb + (size_t)e * DIM_O;
#pragma unroll
    for (int t = 0; t < 2; t++) {
#pragma unroll
        for (int nt = 0; nt < 8; nt++) {
            int col = n0 + wn + 8 * nt + 2 * q;
            float b0v = ebrow[col], b1v = ebrow[col + 1];
            int r = row0 + wm + 16 * t + g;
            float2 v0, v1;
            v0.x = fmaxf(acc[t][nt][0] + b0v, 0.f);
            v0.y = fmaxf(acc[t][nt][1] + b1v, 0.f);
            v1.x = fmaxf(acc[t][nt][2] + b0v, 0.f);
            v1.y = fmaxf(acc[t][nt][3] + b1v, 0.f);
            *(float2*)(g_operm + (size_t)r * DIM_O + col) = v0;
            *(float2*)(g_operm + (size_t)(r + 8) * DIM_O + col) = v1;
        }
    }
}

// ---------------- combine: out[t] = 0.5*(row_e1 + row_e2) ----------------
__global__ void combine_k(float* __restrict__ out) {
    int t = blockIdx.x;
    const float4* a = (const float4*)(g_operm + (size_t)g_pos[2 * t] * DIM_O);
    const float4* b = (const float4*)(g_operm + (size_t)g_pos[2 * t + 1] * DIM_O);
    float4* o = (float4*)(out + (size_t)t * DIM_O);
    for (int i = threadIdx.x; i < DIM_O / 4; i += blockDim.x) {
        float4 va = a[i], vb = b[i];
        float4 v;
        v.x = 0.5f * (va.x + vb.x); v.y = 0.5f * (va.y + vb.y);
        v.z = 0.5f * (va.z + vb.z); v.w = 0.5f * (va.w + vb.w);
        o[i] = v;
    }
}

// ---------------- host ----------------
extern "C" void kernel_launch(void* const* d_in, const int* in_sizes, int n_in,
                              void* d_out, int out_size) {
    const float* x  = (const float*)d_in[0];
    const float* gw = (const float*)d_in[1];
    const float* gb = (const float*)d_in[2];
    const float* ew = (const float*)d_in[3];
    const float* eb = (const float*)d_in[4];
    float* out = (float*)d_out;

    void* p_rows;
    cudaGetSymbolAddress(&p_rows, g_rows);

    init_k<<<1, 32>>>();
    cudaMemsetAsync(p_rows, 0xFF, R_MAX * sizeof(int));
    gate_k<<<T_TOKENS / 8, 256>>>(x, gw, gb);
    scan_k<<<1, 1>>>();
    scatter_k<<<(T_TOKENS * 2) / 256, 256>>>();
    xh_k<<<T_TOKENS * DIM_D / 2048, 256>>>(x);
    wt_k<<<dim3(DIM_D / 64, DIM_O / 64, N_EXP), 256>>>(ew);
    moe_hmma<<<dim3(DIM_O / BN, MAX_TILES), 256>>>(eb);
    combine_k<<<T_TOKENS, 256>>>(out);
}

// round 6
// speedup vs baseline: 5.4305x; 1.3576x over previous
#include <cuda_runtime.h>
#include <cuda_fp16.h>
#include <cstdint>

// Problem: N=8,S=2048 -> T=16384 tokens, D=O=2048, E=8, top-2
#define T_TOKENS 16384
#define DIM_D    2048
#define DIM_O    2048
#define N_EXP    8
#define MAX_TILES 264               // ceil-per-expert padding worst case
#define R_MAX    (MAX_TILES * 128)  // padded rows

#define BM 128
#define BN 128
#define BK 64
#define NSTAGE 3
#define A_STAGE (BM * BK * 2)       // 16384 B
#define B_STAGE (BN * BK * 2)       // 16384 B
#define SMEM_TOTAL (NSTAGE * (A_STAGE + B_STAGE) + 512)

// ---------------- device scratch (static; no allocation) ----------------
__device__ float g_operm[(size_t)R_MAX * DIM_O];            // relu(XW+b) rows
__device__ __half g_xh[(size_t)T_TOKENS * DIM_D];           // x fp16 (token order)
__device__ __half g_wt[(size_t)N_EXP * DIM_O * DIM_D];      // W^T fp16 [e][o][d]
__device__ int g_top[T_TOKENS * 2];
__device__ int g_counts[N_EXP];
__device__ int g_offsets[N_EXP];
__device__ int g_cursor[N_EXP];
__device__ int g_rows[R_MAX];        // padded row -> token (valid only < offset+count)
__device__ int g_pos[T_TOKENS * 2];  // (token,k) -> padded row
__device__ int g_tile_e[MAX_TILES];
__device__ int g_tile_r0[MAX_TILES];
__device__ int g_num_tiles;

// ---------------- helpers ----------------
__device__ __forceinline__ uint32_t smem_u32(const void* p) {
    uint32_t a;
    asm("{ .reg .u64 t; cvta.to.shared.u64 t, %1; cvt.u32.u64 %0, t; }" : "=r"(a) : "l"(p));
    return a;
}
__device__ __forceinline__ void cpa(uint32_t dst, const void* src, int n) {
    asm volatile("cp.async.ca.shared.global [%0], [%1], 16, %2;"
                 :: "r"(dst), "l"(src), "r"(n) : "memory");
}
#define CP_COMMIT() asm volatile("cp.async.commit_group;" ::: "memory")
#define CP_WAIT1()  asm volatile("cp.async.wait_group 1;" ::: "memory")
__device__ __forceinline__ void ldsm4(uint32_t* r, uint32_t addr) {
    asm volatile("ldmatrix.sync.aligned.m8n8.x4.shared.b16 {%0,%1,%2,%3}, [%4];"
                 : "=r"(r[0]), "=r"(r[1]), "=r"(r[2]), "=r"(r[3]) : "r"(addr));
}
__device__ __forceinline__ void mma_f16(float* d, const uint32_t* a, uint32_t b0, uint32_t b1) {
    asm volatile(
        "mma.sync.aligned.m16n8k16.row.col.f32.f16.f16.f32 "
        "{%0,%1,%2,%3}, {%4,%5,%6,%7}, {%8,%9}, {%0,%1,%2,%3};"
        : "+f"(d[0]), "+f"(d[1]), "+f"(d[2]), "+f"(d[3])
        : "r"(a[0]), "r"(a[1]), "r"(a[2]), "r"(a[3]), "r"(b0), "r"(b1));
}
// swizzled byte offset within a stage: row*128 + 16*(chunk ^ (row&7))
__device__ __forceinline__ int swz(int row, int chunk) {
    return row * 128 + ((chunk ^ (row & 7)) << 4);
}

// ---------------- init ----------------
__global__ void init_k() {
    int i = threadIdx.x;
    if (i < N_EXP) { g_counts[i] = 0; g_cursor[i] = 0; }
}

// ---------------- gate (fused x->fp16): fp32 logits + top-2, warp per token ----------------
__global__ void gate_k(const float* __restrict__ x,
                       const float* __restrict__ gw,
                       const float* __restrict__ gb) {
    int warp = (blockIdx.x * blockDim.x + threadIdx.x) >> 5;
    int lane = threadIdx.x & 31;
    if (warp >= T_TOKENS) return;
    const float4* xr = (const float4*)(x + ((size_t)warp << 11));
    __half* xh = g_xh + ((size_t)warp << 11);

    float acc[N_EXP];
#pragma unroll
    for (int e = 0; e < N_EXP; e++) acc[e] = 0.f;

#pragma unroll 4
    for (int i = 0; i < 16; i++) {
        int k4 = lane + 32 * i;
        float4 v = xr[k4];
        union { __half2 h[2]; uint2 u; } o;
        o.h[0] = __floats2half2_rn(v.x, v.y);
        o.h[1] = __floats2half2_rn(v.z, v.w);
        *(uint2*)(xh + 4 * k4) = o.u;
        const float* vv = &v.x;
        const float4* g4 = (const float4*)(gw + ((size_t)(4 * k4)) * N_EXP);
#pragma unroll
        for (int j = 0; j < 4; j++) {
            float xv = vv[j];
            float4 a = g4[2 * j], b = g4[2 * j + 1];
            acc[0] += xv * a.x; acc[1] += xv * a.y; acc[2] += xv * a.z; acc[3] += xv * a.w;
            acc[4] += xv * b.x; acc[5] += xv * b.y; acc[6] += xv * b.z; acc[7] += xv * b.w;
        }
    }
#pragma unroll
    for (int e = 0; e < N_EXP; e++)
#pragma unroll
        for (int off = 16; off; off >>= 1)
            acc[e] += __shfl_xor_sync(0xffffffffu, acc[e], off);
    if (lane == 0) {
        float v1 = -1e30f, v2 = -1e30f; int i1 = 0, i2 = 0;
#pragma unroll
        for (int e = 0; e < N_EXP; e++) {
            float v = acc[e] + gb[e];
            if (v > v1)      { v2 = v1; i2 = i1; v1 = v; i1 = e; }
            else if (v > v2) { v2 = v;  i2 = e; }
        }
        g_top[warp * 2 + 0] = i1;
        g_top[warp * 2 + 1] = i2;
        atomicAdd(&g_counts[i1], 1);
        atomicAdd(&g_counts[i2], 1);
    }
}

// ---------------- scan: padded offsets + tile table ----------------
__global__ void scan_k() {
    if (threadIdx.x != 0) return;
    int o = 0, t = 0;
    for (int e = 0; e < N_EXP; e++) {
        g_offsets[e] = o;
        int nt = (g_counts[e] + 127) / 128;
        for (int i = 0; i < nt; i++) { g_tile_e[t] = e; g_tile_r0[t] = o + i * 128; t++; }
        o += nt * 128;
    }
    g_num_tiles = t;
}

// ---------------- scatter ----------------
__global__ void scatter_k() {
    int i = blockIdx.x * blockDim.x + threadIdx.x;
    if (i >= T_TOKENS * 2) return;
    int e = g_top[i];
    int pos = atomicAdd(&g_cursor[e], 1);
    int row = g_offsets[e] + pos;
    g_rows[row] = i >> 1;
    g_pos[i] = row;
}

// ---------------- transpose+convert W[e][d][o] -> Wt[e][o][d] fp16 ----------------
__global__ void wt_k(const float* __restrict__ w) {
    __shared__ float tf[64][65];
    int e = blockIdx.z;
    int d0 = blockIdx.x * 64, o0 = blockIdx.y * 64;
    const float* we = w + ((size_t)e * DIM_D + d0) * DIM_O + o0;
    int dd = threadIdx.x >> 2, oq = (threadIdx.x & 3) * 16;
#pragma unroll
    for (int c = 0; c < 4; c++) {
        float4 v = *(const float4*)(we + (size_t)dd * DIM_O + oq + 4 * c);
        tf[dd][oq + 4 * c + 0] = v.x; tf[dd][oq + 4 * c + 1] = v.y;
        tf[dd][oq + 4 * c + 2] = v.z; tf[dd][oq + 4 * c + 3] = v.w;
    }
    __syncthreads();
    int oo = threadIdx.x >> 2, dq = (threadIdx.x & 3) * 16;
    union { __half2 h[8]; uint4 u[2]; } ou;
#pragma unroll
    for (int j = 0; j < 8; j++)
        ou.h[j] = __floats2half2_rn(tf[dq + 2 * j][oo], tf[dq + 2 * j + 1][oo]);
    size_t off = ((size_t)e * DIM_O + o0 + oo) * DIM_D + d0 + dq;
    *(uint4*)(g_wt + off) = ou.u[0];
    *(uint4*)(g_wt + off + 8) = ou.u[1];
}

// ---------------- grouped GEMM: fp16 mma.sync + cp.async 3-stage + ldmatrix ----------------
__global__ void __launch_bounds__(256, 2)
moe_hmma(const float* __restrict__ eb) {
    int mt = blockIdx.y;
    if (mt >= g_num_tiles) return;
    int e    = g_tile_e[mt];
    int row0 = g_tile_r0[mt];
    int n0   = blockIdx.x * BN;
    int lim  = g_offsets[e] + g_counts[e];

    extern __shared__ char sm[];
    char* Asm = sm;
    char* Bsm = sm + NSTAGE * A_STAGE;
    int* toks = (int*)(sm + NSTAGE * (A_STAGE + B_STAGE));
    uint32_t sbA = smem_u32(Asm);
    uint32_t sbB = smem_u32(Bsm);

    int tid = threadIdx.x;
    if (tid < BM) toks[tid] = (row0 + tid < lim) ? g_rows[row0 + tid] : -1;
    __syncthreads();

    // ---- producer mapping: thread -> (rows prow+32i, 16B chunk pc) ----
    int prow = tid >> 3;
    int pc   = tid & 7;
    int atok[4];
    const __half* asrc[4];
    const __half* bsrc[4];
    int adst[4], bdst[4];
#pragma unroll
    for (int i = 0; i < 4; i++) {
        int r = prow + 32 * i;
        atok[i] = toks[r];
        int t = atok[i] < 0 ? 0 : atok[i];
        asrc[i] = g_xh + ((size_t)t << 11) + 8 * pc;
        bsrc[i] = g_wt + ((size_t)e * DIM_O + n0 + r) * DIM_D + 8 * pc;
        adst[i] = swz(r, pc);
        bdst[i] = swz(r, pc);
    }

    // ---- warp / fragment mapping ----
    int warp = tid >> 5, lane = tid & 31;
    int wm = (warp & 3) * 32;    // 4 M-warps x 2 m16 tiles
    int wn = (warp >> 2) * 64;   // 2 N-warps x 8 n8 tiles
    int arow  = wm + ((lane >> 3) & 1) * 8 + (lane & 7);
    int achi  = lane >> 4;
    int brow_ = ((lane >> 4) << 3) + (lane & 7);
    int bchi  = (lane >> 3) & 1;

    float acc[2][8][4];
#pragma unroll
    for (int t = 0; t < 2; t++)
#pragma unroll
        for (int n = 0; n < 8; n++)
#pragma unroll
            for (int j = 0; j < 4; j++) acc[t][n][j] = 0.f;

    const int NKI = DIM_D / BK;  // 32

    // ---- prologue: stages 0,1 ----
#pragma unroll
    for (int s = 0; s < 2; s++) {
        int k0 = s * BK;
#pragma unroll
        for (int i = 0; i < 4; i++) {
            cpa(sbA + s * A_STAGE + adst[i], asrc[i] + k0, atok[i] >= 0 ? 16 : 0);
            cpa(sbB + s * B_STAGE + bdst[i], bsrc[i] + k0, 16);
        }
        CP_COMMIT();
    }

    int st = 0;
    for (int ks = 0; ks < NKI; ks++) {
        CP_WAIT1();
        __syncthreads();

        // issue stage ks+2
        int kn = ks + 2;
        if (kn < NKI) {
            int sn = st + 2; if (sn >= NSTAGE) sn -= NSTAGE;
            int k0 = kn * BK;
#pragma unroll
            for (int i = 0; i < 4; i++) {
                cpa(sbA + sn * A_STAGE + adst[i], asrc[i] + k0, atok[i] >= 0 ? 16 : 0);
                cpa(sbB + sn * B_STAGE + bdst[i], bsrc[i] + k0, 16);
            }
        }
        CP_COMMIT();

        // compute stage st
        uint32_t ab = sbA + st * A_STAGE;
        uint32_t bb = sbB + st * B_STAGE;
#pragma unroll
        for (int kb = 0; kb < 4; kb++) {
            uint32_t a[2][4];
#pragma unroll
            for (int tt = 0; tt < 2; tt++)
                ldsm4(a[tt], ab + swz(arow + 16 * tt, 2 * kb + achi));
#pragma unroll
            for (int ntp = 0; ntp < 4; ntp++) {
                uint32_t b[4];
                ldsm4(b, bb + swz(wn + 16 * ntp + brow_, 2 * kb + bchi));
                mma_f16(acc[0][2 * ntp],     a[0], b[0], b[1]);
                mma_f16(acc[0][2 * ntp + 1], a[0], b[2], b[3]);
                mma_f16(acc[1][2 * ntp],     a[1], b[0], b[1]);
                mma_f16(acc[1][2 * ntp + 1], a[1], b[2], b[3]);
            }
        }
        if (++st == NSTAGE) st = 0;
    }

    // ---- epilogue: relu(acc + bias) -> g_operm ----
    int g = lane >> 2, q = lane & 3;
    const float* ebrow = eb + (size_t)e * DIM_O;
#pragma unroll
    for (int t = 0; t < 2; t++) {
#pragma unroll
        for (int nt = 0; nt < 8; nt++) {
            int col = n0 + wn + 8 * nt + 2 * q;
            float b0v = ebrow[col], b1v = ebrow[col + 1];
            int r = row0 + wm + 16 * t + g;
            float2 v0, v1;
            v0.x = fmaxf(acc[t][nt][0] + b0v, 0.f);
            v0.y = fmaxf(acc[t][nt][1] + b1v, 0.f);
            v1.x = fmaxf(acc[t][nt][2] + b0v, 0.f);
            v1.y = fmaxf(acc[t][nt][3] + b1v, 0.f);
            *(float2*)(g_operm + (size_t)r * DIM_O + col) = v0;
            *(float2*)(g_operm + (size_t)(r + 8) * DIM_O + col) = v1;
        }
    }
}

// ---------------- combine: out[t] = 0.5*(row_e1 + row_e2) ----------------
__global__ void combine_k(float* __restrict__ out) {
    int t = blockIdx.x;
    const float4* a = (const float4*)(g_operm + (size_t)g_pos[2 * t] * DIM_O);
    const float4* b = (const float4*)(g_operm + (size_t)g_pos[2 * t + 1] * DIM_O);
    float4* o = (float4*)(out + (size_t)t * DIM_O);
    for (int i = threadIdx.x; i < DIM_O / 4; i += blockDim.x) {
        float4 va = a[i], vb = b[i];
        float4 v;
        v.x = 0.5f * (va.x + vb.x); v.y = 0.5f * (va.y + vb.y);
        v.z = 0.5f * (va.z + vb.z); v.w = 0.5f * (va.w + vb.w);
        o[i] = v;
    }
}

// ---------------- host ----------------
extern "C" void kernel_launch(void* const* d_in, const int* in_sizes, int n_in,
                              void* d_out, int out_size) {
    const float* x  = (const float*)d_in[0];
    const float* gw = (const float*)d_in[1];
    const float* gb = (const float*)d_in[2];
    const float* ew = (const float*)d_in[3];
    const float* eb = (const float*)d_in[4];
    float* out = (float*)d_out;

    cudaFuncSetAttribute(moe_hmma, cudaFuncAttributeMaxDynamicSharedMemorySize, SMEM_TOTAL);

    init_k<<<1, 32>>>();                                   // 1
    gate_k<<<T_TOKENS / 8, 256>>>(x, gw, gb);              // 2 (also writes g_xh)
    scan_k<<<1, 1>>>();                                    // 3
    scatter_k<<<(T_TOKENS * 2) / 256, 256>>>();            // 4
    wt_k<<<dim3(DIM_D / 64, DIM_O / 64, N_EXP), 256>>>(ew);// 5
    moe_hmma<<<dim3(DIM_O / BN, MAX_TILES), 256, SMEM_TOTAL>>>(eb);  // 6 <- ncu target
    combine_k<<<T_TOKENS, 256>>>(out);                     // 7
}

// round 7
// speedup vs baseline: 5.4480x; 1.0032x over previous
#include <cuda_runtime.h>
#include <cuda_fp16.h>
#include <cstdint>

// Problem: N=8,S=2048 -> T=16384 tokens, D=O=2048, E=8, top-2
#define T_TOKENS 16384
#define DIM_D    2048
#define DIM_O    2048
#define N_EXP    8
#define MAX_TILES 264               // ceil-per-expert padding worst case
#define R_MAX    (MAX_TILES * 128)  // padded rows

#define BM 128
#define BN 256
#define BK 64
#define NSTAGE 3
#define A_STAGE (BM * BK * 2)       // 16384 B
#define B_STAGE (BN * BK * 2)       // 32768 B
#define SMEM_TOTAL (NSTAGE * (A_STAGE + B_STAGE) + 512)

// ---------------- device scratch (static; no allocation) ----------------
__device__ __half g_operm[(size_t)R_MAX * DIM_O];           // relu(XW+b) rows (fp16)
__device__ __half g_xh[(size_t)T_TOKENS * DIM_D];           // x fp16 (token order)
__device__ __half g_wt[(size_t)N_EXP * DIM_O * DIM_D];      // W^T fp16 [e][o][d]
__device__ int g_top[T_TOKENS * 2];
__device__ int g_counts[N_EXP];
__device__ int g_offsets[N_EXP];
__device__ int g_cursor[N_EXP];
__device__ int g_rows[R_MAX];        // padded row -> token (valid only < offset+count)
__device__ int g_pos[T_TOKENS * 2];  // (token,k) -> padded row
__device__ int g_tile_e[MAX_TILES];
__device__ int g_tile_r0[MAX_TILES];
__device__ int g_num_tiles;

// ---------------- helpers ----------------
__device__ __forceinline__ uint32_t smem_u32(const void* p) {
    uint32_t a;
    asm("{ .reg .u64 t; cvta.to.shared.u64 t, %1; cvt.u32.u64 %0, t; }" : "=r"(a) : "l"(p));
    return a;
}
__device__ __forceinline__ void cpa(uint32_t dst, const void* src, int n) {
    asm volatile("cp.async.ca.shared.global [%0], [%1], 16, %2;"
                 :: "r"(dst), "l"(src), "r"(n) : "memory");
}
#define CP_COMMIT() asm volatile("cp.async.commit_group;" ::: "memory")
#define CP_WAIT1()  asm volatile("cp.async.wait_group 1;" ::: "memory")
__device__ __forceinline__ void ldsm4(uint32_t* r, uint32_t addr) {
    asm volatile("ldmatrix.sync.aligned.m8n8.x4.shared.b16 {%0,%1,%2,%3}, [%4];"
                 : "=r"(r[0]), "=r"(r[1]), "=r"(r[2]), "=r"(r[3]) : "r"(addr));
}
__device__ __forceinline__ void mma_f16(float* d, const uint32_t* a, uint32_t b0, uint32_t b1) {
    asm volatile(
        "mma.sync.aligned.m16n8k16.row.col.f32.f16.f16.f32 "
        "{%0,%1,%2,%3}, {%4,%5,%6,%7}, {%8,%9}, {%0,%1,%2,%3};"
        : "+f"(d[0]), "+f"(d[1]), "+f"(d[2]), "+f"(d[3])
        : "r"(a[0]), "r"(a[1]), "r"(a[2]), "r"(a[3]), "r"(b0), "r"(b1));
}
// swizzled byte offset within a stage: row*128 + 16*(chunk ^ (row&7))
__device__ __forceinline__ int swz(int row, int chunk) {
    return row * 128 + ((chunk ^ (row & 7)) << 4);
}

// ---------------- init ----------------
__global__ void init_k() {
    int i = threadIdx.x;
    if (i < N_EXP) { g_counts[i] = 0; g_cursor[i] = 0; }
}

// ---------------- gate (fused x->fp16): fp32 logits + top-2, warp per token ----------------
__global__ void gate_k(const float* __restrict__ x,
                       const float* __restrict__ gw,
                       const float* __restrict__ gb) {
    int warp = (blockIdx.x * blockDim.x + threadIdx.x) >> 5;
    int lane = threadIdx.x & 31;
    if (warp >= T_TOKENS) return;
    const float4* xr = (const float4*)(x + ((size_t)warp << 11));
    __half* xh = g_xh + ((size_t)warp << 11);

    float acc[N_EXP];
#pragma unroll
    for (int e = 0; e < N_EXP; e++) acc[e] = 0.f;

#pragma unroll 4
    for (int i = 0; i < 16; i++) {
        int k4 = lane + 32 * i;
        float4 v = xr[k4];
        union { __half2 h[2]; uint2 u; } o;
        o.h[0] = __floats2half2_rn(v.x, v.y);
        o.h[1] = __floats2half2_rn(v.z, v.w);
        *(uint2*)(xh + 4 * k4) = o.u;
        const float* vv = &v.x;
        const float4* g4 = (const float4*)(gw + ((size_t)(4 * k4)) * N_EXP);
#pragma unroll
        for (int j = 0; j < 4; j++) {
            float xv = vv[j];
            float4 a = g4[2 * j], b = g4[2 * j + 1];
            acc[0] += xv * a.x; acc[1] += xv * a.y; acc[2] += xv * a.z; acc[3] += xv * a.w;
            acc[4] += xv * b.x; acc[5] += xv * b.y; acc[6] += xv * b.z; acc[7] += xv * b.w;
        }
    }
#pragma unroll
    for (int e = 0; e < N_EXP; e++)
#pragma unroll
        for (int off = 16; off; off >>= 1)
            acc[e] += __shfl_xor_sync(0xffffffffu, acc[e], off);
    if (lane == 0) {
        float v1 = -1e30f, v2 = -1e30f; int i1 = 0, i2 = 0;
#pragma unroll
        for (int e = 0; e < N_EXP; e++) {
            float v = acc[e] + gb[e];
            if (v > v1)      { v2 = v1; i2 = i1; v1 = v; i1 = e; }
            else if (v > v2) { v2 = v;  i2 = e; }
        }
        g_top[warp * 2 + 0] = i1;
        g_top[warp * 2 + 1] = i2;
        atomicAdd(&g_counts[i1], 1);
        atomicAdd(&g_counts[i2], 1);
    }
}

// ---------------- scan: padded offsets + tile table ----------------
__global__ void scan_k() {
    if (threadIdx.x != 0) return;
    int o = 0, t = 0;
    for (int e = 0; e < N_EXP; e++) {
        g_offsets[e] = o;
        int nt = (g_counts[e] + 127) / 128;
        for (int i = 0; i < nt; i++) { g_tile_e[t] = e; g_tile_r0[t] = o + i * 128; t++; }
        o += nt * 128;
    }
    g_num_tiles = t;
}

// ---------------- scatter ----------------
__global__ void scatter_k() {
    int i = blockIdx.x * blockDim.x + threadIdx.x;
    if (i >= T_TOKENS * 2) return;
    int e = g_top[i];
    int pos = atomicAdd(&g_cursor[e], 1);
    int row = g_offsets[e] + pos;
    g_rows[row] = i >> 1;
    g_pos[i] = row;
}

// ---------------- transpose+convert W[e][d][o] -> Wt[e][o][d] fp16 ----------------
__global__ void wt_k(const float* __restrict__ w) {
    __shared__ float tf[64][65];
    int e = blockIdx.z;
    int d0 = blockIdx.x * 64, o0 = blockIdx.y * 64;
    const float* we = w + ((size_t)e * DIM_D + d0) * DIM_O + o0;
    int dd = threadIdx.x >> 2, oq = (threadIdx.x & 3) * 16;
#pragma unroll
    for (int c = 0; c < 4; c++) {
        float4 v = *(const float4*)(we + (size_t)dd * DIM_O + oq + 4 * c);
        tf[dd][oq + 4 * c + 0] = v.x; tf[dd][oq + 4 * c + 1] = v.y;
        tf[dd][oq + 4 * c + 2] = v.z; tf[dd][oq + 4 * c + 3] = v.w;
    }
    __syncthreads();
    int oo = threadIdx.x >> 2, dq = (threadIdx.x & 3) * 16;
    union { __half2 h[8]; uint4 u[2]; } ou;
#pragma unroll
    for (int j = 0; j < 8; j++)
        ou.h[j] = __floats2half2_rn(tf[dq + 2 * j][oo], tf[dq + 2 * j + 1][oo]);
    size_t off = ((size_t)e * DIM_O + o0 + oo) * DIM_D + d0 + dq;
    *(uint4*)(g_wt + off) = ou.u[0];
    *(uint4*)(g_wt + off + 8) = ou.u[1];
}

// ---------------- grouped GEMM: fp16 mma.sync, BM=128 BN=256, 3-stage cp.async ----------------
__global__ void __launch_bounds__(256, 1)
moe_hmma(const float* __restrict__ eb) {
    int mt = blockIdx.y;
    if (mt >= g_num_tiles) return;
    int e    = g_tile_e[mt];
    int row0 = g_tile_r0[mt];
    int n0   = blockIdx.x * BN;
    int lim  = g_offsets[e] + g_counts[e];

    extern __shared__ char sm[];
    char* Asm = sm;
    char* Bsm = sm + NSTAGE * A_STAGE;
    int* toks = (int*)(sm + NSTAGE * (A_STAGE + B_STAGE));
    uint32_t sbA = smem_u32(Asm);
    uint32_t sbB = smem_u32(Bsm);

    int tid = threadIdx.x;
    if (tid < BM) toks[tid] = (row0 + tid < lim) ? g_rows[row0 + tid] : -1;
    __syncthreads();

    // ---- producer mapping: thread -> (row prow+32i, 16B chunk pc) ----
    int prow = tid >> 3;          // 0..31
    int pc   = tid & 7;           // 16B chunk within 128B row
    int atok[4];
    const __half* asrc[4];
    int adst[4];
#pragma unroll
    for (int i = 0; i < 4; i++) {
        int r = prow + 32 * i;
        atok[i] = toks[r];
        int t = atok[i] < 0 ? 0 : atok[i];
        asrc[i] = g_xh + ((size_t)t << 11) + 8 * pc;
        adst[i] = swz(r, pc);
    }
    const __half* bsrc[8];
    int bdst[8];
#pragma unroll
    for (int i = 0; i < 8; i++) {
        int r = prow + 32 * i;
        bsrc[i] = g_wt + ((size_t)e * DIM_O + n0 + r) * DIM_D + 8 * pc;
        bdst[i] = swz(r, pc);
    }

    // ---- warp / fragment mapping: 4 M-warps x 2 N-warps, warp tile 32x128 ----
    int warp = tid >> 5, lane = tid & 31;
    int wm = (warp & 3) * 32;
    int wn = (warp >> 2) * 128;
    int arow  = wm + ((lane >> 3) & 1) * 8 + (lane & 7);
    int achi  = lane >> 4;
    int brow_ = ((lane >> 4) << 3) + (lane & 7);
    int bchi  = (lane >> 3) & 1;

    float acc[2][16][4];
#pragma unroll
    for (int t = 0; t < 2; t++)
#pragma unroll
        for (int n = 0; n < 16; n++)
#pragma unroll
            for (int j = 0; j < 4; j++) acc[t][n][j] = 0.f;

    const int NKI = DIM_D / BK;  // 32

    // ---- prologue: stages 0,1 ----
#pragma unroll
    for (int s = 0; s < 2; s++) {
        int k0 = s * BK;
#pragma unroll
        for (int i = 0; i < 4; i++)
            cpa(sbA + s * A_STAGE + adst[i], asrc[i] + k0, atok[i] >= 0 ? 16 : 0);
#pragma unroll
        for (int i = 0; i < 8; i++)
            cpa(sbB + s * B_STAGE + bdst[i], bsrc[i] + k0, 16);
        CP_COMMIT();
    }

    int st = 0;
    for (int ks = 0; ks < NKI; ks++) {
        CP_WAIT1();
        __syncthreads();

        // issue stage ks+2
        int kn = ks + 2;
        if (kn < NKI) {
            int sn = st + 2; if (sn >= NSTAGE) sn -= NSTAGE;
            int k0 = kn * BK;
#pragma unroll
            for (int i = 0; i < 4; i++)
                cpa(sbA + sn * A_STAGE + adst[i], asrc[i] + k0, atok[i] >= 0 ? 16 : 0);
#pragma unroll
            for (int i = 0; i < 8; i++)
                cpa(sbB + sn * B_STAGE + bdst[i], bsrc[i] + k0, 16);
        }
        CP_COMMIT();

        // compute stage st
        uint32_t ab = sbA + st * A_STAGE;
        uint32_t bb = sbB + st * B_STAGE;
#pragma unroll
        for (int kb = 0; kb < 4; kb++) {
            uint32_t a[2][4];
#pragma unroll
            for (int tt = 0; tt < 2; tt++)
                ldsm4(a[tt], ab + swz(arow + 16 * tt, 2 * kb + achi));
#pragma unroll
            for (int ntp = 0; ntp < 8; ntp++) {
                uint32_t b[4];
                ldsm4(b, bb + swz(wn + 16 * ntp + brow_, 2 * kb + bchi));
                mma_f16(acc[0][2 * ntp],     a[0], b[0], b[1]);
                mma_f16(acc[0][2 * ntp + 1], a[0], b[2], b[3]);
                mma_f16(acc[1][2 * ntp],     a[1], b[0], b[1]);
                mma_f16(acc[1][2 * ntp + 1], a[1], b[2], b[3]);
            }
        }
        if (++st == NSTAGE) st = 0;
    }

    // ---- epilogue: relu(acc + bias) -> g_operm (fp16) ----
    int g = lane >> 2, q = lane & 3;
    const float* ebrow = eb + (size_t)e * DIM_O;
#pragma unroll
    for (int t = 0; t < 2; t++) {
#pragma unroll
        for (int nt = 0; nt < 16; nt++) {
            int col = n0 + wn + 8 * nt + 2 * q;
            float b0v = ebrow[col], b1v = ebrow[col + 1];
            int r = row0 + wm + 16 * t + g;
            __half2 h0 = __floats2half2_rn(fmaxf(acc[t][nt][0] + b0v, 0.f),
                                           fmaxf(acc[t][nt][1] + b1v, 0.f));
            __half2 h1 = __floats2half2_rn(fmaxf(acc[t][nt][2] + b0v, 0.f),
                                           fmaxf(acc[t][nt][3] + b1v, 0.f));
            *(__half2*)(g_operm + (size_t)r * DIM_O + col) = h0;
            *(__half2*)(g_operm + (size_t)(r + 8) * DIM_O + col) = h1;
        }
    }
}

// ---------------- combine: out[t] = 0.5*(row_e1 + row_e2) ----------------
__global__ void combine_k(float* __restrict__ out) {
    int t = blockIdx.x;
    const uint4* a = (const uint4*)(g_operm + (size_t)g_pos[2 * t] * DIM_O);
    const uint4* b = (const uint4*)(g_operm + (size_t)g_pos[2 * t + 1] * DIM_O);
    float4* o = (float4*)(out + (size_t)t * DIM_O);
    int i = threadIdx.x;   // 256 threads x 8 halves = 2048
    union { uint4 u; __half2 h[4]; } va, vb;
    va.u = a[i]; vb.u = b[i];
#pragma unroll
    for (int j = 0; j < 4; j += 2) {
        float2 a0 = __half22float2(va.h[j]),     b0 = __half22float2(vb.h[j]);
        float2 a1 = __half22float2(va.h[j + 1]), b1 = __half22float2(vb.h[j + 1]);
        float4 v;
        v.x = 0.5f * (a0.x + b0.x); v.y = 0.5f * (a0.y + b0.y);
        v.z = 0.5f * (a1.x + b1.x); v.w = 0.5f * (a1.y + b1.y);
        o[2 * i + j / 2] = v;
    }
}

// ---------------- host ----------------
extern "C" void kernel_launch(void* const* d_in, const int* in_sizes, int n_in,
                              void* d_out, int out_size) {
    const float* x  = (const float*)d_in[0];
    const float* gw = (const float*)d_in[1];
    const float* gb = (const float*)d_in[2];
    const float* ew = (const float*)d_in[3];
    const float* eb = (const float*)d_in[4];
    float* out = (float*)d_out;

    cudaFuncSetAttribute(moe_hmma, cudaFuncAttributeMaxDynamicSharedMemorySize, SMEM_TOTAL);

    init_k<<<1, 32>>>();                                    // 1
    gate_k<<<T_TOKENS / 8, 256>>>(x, gw, gb);               // 2 (also writes g_xh)
    scan_k<<<1, 1>>>();                                     // 3
    scatter_k<<<(T_TOKENS * 2) / 256, 256>>>();             // 4
    wt_k<<<dim3(DIM_D / 64, DIM_O / 64, N_EXP), 256>>>(ew); // 5
    moe_hmma<<<dim3(DIM_O / BN, MAX_TILES), 256, SMEM_TOTAL>>>(eb);  // 6
    combine_k<<<T_TOKENS, 256>>>(out);                      // 7
}

// round 8
// speedup vs baseline: 5.4967x; 1.0089x over previous
#include <cuda_runtime.h>
#include <cuda_fp16.h>
#include <cstdint>

// Problem: N=8,S=2048 -> T=16384 tokens, D=O=2048, E=8, top-2
#define T_TOKENS 16384
#define DIM_D    2048
#define DIM_O    2048
#define N_EXP    8
#define MAX_TILES 264               // ceil-per-expert padding worst case
#define R_MAX    (MAX_TILES * 128)  // padded rows

#define BM 128
#define BN 256
#define BK 64
#define NSTAGE 3
#define A_STAGE (BM * BK * 2)       // 16384 B
#define B_STAGE (BN * BK * 2)       // 32768 B
#define SMEM_TOTAL (NSTAGE * (A_STAGE + B_STAGE) + 512)

#define GATE_BLKS (T_TOKENS / 8)    // 2048
#define WT_BLKS   (32 * 32 * N_EXP) // 8192

// ---------------- device scratch (static; no allocation) ----------------
__device__ __half g_operm[(size_t)R_MAX * DIM_O];           // relu(XW+b) rows (fp16)
__device__ __half g_xh[(size_t)T_TOKENS * DIM_D];           // x fp16 (token order)
__device__ __half g_wt[(size_t)N_EXP * DIM_O * DIM_D];      // W^T fp16 [e][o][d]
__device__ int g_top[T_TOKENS * 2];
__device__ int g_counts[N_EXP];
__device__ int g_offsets[N_EXP];
__device__ int g_cursor[N_EXP];
__device__ int g_rows[R_MAX];        // padded row -> token (valid only < offset+count)
__device__ int g_pos[T_TOKENS * 2];  // (token,k) -> padded row
__device__ int g_tile_e[MAX_TILES];
__device__ int g_tile_r0[MAX_TILES];
__device__ int g_num_tiles;

// ---------------- helpers ----------------
__device__ __forceinline__ uint32_t smem_u32(const void* p) {
    uint32_t a;
    asm("{ .reg .u64 t; cvta.to.shared.u64 t, %1; cvt.u32.u64 %0, t; }" : "=r"(a) : "l"(p));
    return a;
}
__device__ __forceinline__ void cpa(uint32_t dst, const void* src, int n) {
    asm volatile("cp.async.ca.shared.global [%0], [%1], 16, %2;"
                 :: "r"(dst), "l"(src), "r"(n) : "memory");
}
#define CP_COMMIT() asm volatile("cp.async.commit_group;" ::: "memory")
#define CP_WAIT1()  asm volatile("cp.async.wait_group 1;" ::: "memory")
__device__ __forceinline__ void ldsm4(uint32_t* r, uint32_t addr) {
    asm volatile("ldmatrix.sync.aligned.m8n8.x4.shared.b16 {%0,%1,%2,%3}, [%4];"
                 : "=r"(r[0]), "=r"(r[1]), "=r"(r[2]), "=r"(r[3]) : "r"(addr));
}
__device__ __forceinline__ void mma_f16(float* d, const uint32_t* a, uint32_t b0, uint32_t b1) {
    asm volatile(
        "mma.sync.aligned.m16n8k16.row.col.f32.f16.f16.f32 "
        "{%0,%1,%2,%3}, {%4,%5,%6,%7}, {%8,%9}, {%0,%1,%2,%3};"
        : "+f"(d[0]), "+f"(d[1]), "+f"(d[2]), "+f"(d[3])
        : "r"(a[0]), "r"(a[1]), "r"(a[2]), "r"(a[3]), "r"(b0), "r"(b1));
}
// swizzled byte offset within a stage: row*128 + 16*(chunk ^ (row&7))
__device__ __forceinline__ int swz(int row, int chunk) {
    return row * 128 + ((chunk ^ (row & 7)) << 4);
}

// ---------------- init ----------------
__global__ void init_k() {
    int i = threadIdx.x;
    if (i < N_EXP) { g_counts[i] = 0; g_cursor[i] = 0; }
}

// ---------------- fused prep: gate(+x->fp16)  ||  W transpose+convert ----------------
// blocks [0, GATE_BLKS): gate, 8 tokens per block (1 warp each)
// blocks [GATE_BLKS, GATE_BLKS+WT_BLKS): 64x64 W transpose tiles
__global__ void prep_k(const float* __restrict__ x,
                       const float* __restrict__ gw,
                       const float* __restrict__ gb,
                       const float* __restrict__ ew) {
    __shared__ float tf[64][65];

    if (blockIdx.x < GATE_BLKS) {
        // ===== gate part =====
        int warp = (blockIdx.x * blockDim.x + threadIdx.x) >> 5;
        int lane = threadIdx.x & 31;
        const float4* xr = (const float4*)(x + ((size_t)warp << 11));
        __half* xh = g_xh + ((size_t)warp << 11);

        float acc[N_EXP];
#pragma unroll
        for (int e = 0; e < N_EXP; e++) acc[e] = 0.f;

#pragma unroll 8
        for (int i = 0; i < 16; i++) {
            int k4 = lane + 32 * i;
            float4 v = xr[k4];
            union { __half2 h[2]; uint2 u; } o;
            o.h[0] = __floats2half2_rn(v.x, v.y);
            o.h[1] = __floats2half2_rn(v.z, v.w);
            *(uint2*)(xh + 4 * k4) = o.u;
            const float* vv = &v.x;
            const float4* g4 = (const float4*)(gw + ((size_t)(4 * k4)) * N_EXP);
#pragma unroll
            for (int j = 0; j < 4; j++) {
                float xv = vv[j];
                float4 a = g4[2 * j], b = g4[2 * j + 1];
                acc[0] += xv * a.x; acc[1] += xv * a.y; acc[2] += xv * a.z; acc[3] += xv * a.w;
                acc[4] += xv * b.x; acc[5] += xv * b.y; acc[6] += xv * b.z; acc[7] += xv * b.w;
            }
        }
#pragma unroll
        for (int e = 0; e < N_EXP; e++)
#pragma unroll
            for (int off = 16; off; off >>= 1)
                acc[e] += __shfl_xor_sync(0xffffffffu, acc[e], off);
        if (lane == 0) {
            float v1 = -1e30f, v2 = -1e30f; int i1 = 0, i2 = 0;
#pragma unroll
            for (int e = 0; e < N_EXP; e++) {
                float v = acc[e] + gb[e];
                if (v > v1)      { v2 = v1; i2 = i1; v1 = v; i1 = e; }
                else if (v > v2) { v2 = v;  i2 = e; }
            }
            g_top[warp * 2 + 0] = i1;
            g_top[warp * 2 + 1] = i2;
            atomicAdd(&g_counts[i1], 1);
            atomicAdd(&g_counts[i2], 1);
        }
    } else {
        // ===== W transpose+convert part: Wt[e][o][d] = fp16(W[e][d][o]) =====
        int b = blockIdx.x - GATE_BLKS;
        int e = b >> 10;               // 1024 tiles per expert
        int rem = b & 1023;
        int d0 = (rem & 31) * 64, o0 = (rem >> 5) * 64;
        const float* we = ew + ((size_t)e * DIM_D + d0) * DIM_O + o0;
        int dd = threadIdx.x >> 2, oq = (threadIdx.x & 3) * 16;
#pragma unroll
        for (int c = 0; c < 4; c++) {
            float4 v = *(const float4*)(we + (size_t)dd * DIM_O + oq + 4 * c);
            tf[dd][oq + 4 * c + 0] = v.x; tf[dd][oq + 4 * c + 1] = v.y;
            tf[dd][oq + 4 * c + 2] = v.z; tf[dd][oq + 4 * c + 3] = v.w;
        }
        __syncthreads();
        int oo = threadIdx.x >> 2, dq = (threadIdx.x & 3) * 16;
        union { __half2 h[8]; uint4 u[2]; } ou;
#pragma unroll
        for (int j = 0; j < 8; j++)
            ou.h[j] = __floats2half2_rn(tf[dq + 2 * j][oo], tf[dq + 2 * j + 1][oo]);
        size_t off = ((size_t)e * DIM_O + o0 + oo) * DIM_D + d0 + dq;
        *(uint4*)(g_wt + off) = ou.u[0];
        *(uint4*)(g_wt + off + 8) = ou.u[1];
    }
}

// ---------------- scan: padded offsets + tile table ----------------
__global__ void scan_k() {
    if (threadIdx.x != 0) return;
    int o = 0, t = 0;
    for (int e = 0; e < N_EXP; e++) {
        g_offsets[e] = o;
        int nt = (g_counts[e] + 127) / 128;
        for (int i = 0; i < nt; i++) { g_tile_e[t] = e; g_tile_r0[t] = o + i * 128; t++; }
        o += nt * 128;
    }
    g_num_tiles = t;
}

// ---------------- scatter ----------------
__global__ void scatter_k() {
    int i = blockIdx.x * blockDim.x + threadIdx.x;
    if (i >= T_TOKENS * 2) return;
    int e = g_top[i];
    int pos = atomicAdd(&g_cursor[e], 1);
    int row = g_offsets[e] + pos;
    g_rows[row] = i >> 1;
    g_pos[i] = row;
}

// ---------------- grouped GEMM: fp16 mma.sync, BM=128 BN=256, 3-stage cp.async ----------------
__global__ void __launch_bounds__(256, 1)
moe_hmma(const float* __restrict__ eb) {
    int mt = blockIdx.y;
    if (mt >= g_num_tiles) return;
    int e    = g_tile_e[mt];
    int row0 = g_tile_r0[mt];
    int n0   = blockIdx.x * BN;
    int lim  = g_offsets[e] + g_counts[e];

    extern __shared__ char sm[];
    char* Asm = sm;
    char* Bsm = sm + NSTAGE * A_STAGE;
    int* toks = (int*)(sm + NSTAGE * (A_STAGE + B_STAGE));
    uint32_t sbA = smem_u32(Asm);
    uint32_t sbB = smem_u32(Bsm);

    int tid = threadIdx.x;
    if (tid < BM) toks[tid] = (row0 + tid < lim) ? g_rows[row0 + tid] : -1;
    __syncthreads();

    // ---- producer mapping: thread -> (row prow+32i, 16B chunk pc) ----
    int prow = tid >> 3;          // 0..31
    int pc   = tid & 7;           // 16B chunk within 128B row
    int atok[4];
    const __half* asrc[4];
    int adst[4];
#pragma unroll
    for (int i = 0; i < 4; i++) {
        int r = prow + 32 * i;
        atok[i] = toks[r];
        int t = atok[i] < 0 ? 0 : atok[i];
        asrc[i] = g_xh + ((size_t)t << 11) + 8 * pc;
        adst[i] = swz(r, pc);
    }
    const __half* bsrc[8];
    int bdst[8];
#pragma unroll
    for (int i = 0; i < 8; i++) {
        int r = prow + 32 * i;
        bsrc[i] = g_wt + ((size_t)e * DIM_O + n0 + r) * DIM_D + 8 * pc;
        bdst[i] = swz(r, pc);
    }

    // ---- warp / fragment mapping: 4 M-warps x 2 N-warps, warp tile 32x128 ----
    int warp = tid >> 5, lane = tid & 31;
    int wm = (warp & 3) * 32;
    int wn = (warp >> 2) * 128;
    int arow  = wm + ((lane >> 3) & 1) * 8 + (lane & 7);
    int achi  = lane >> 4;
    int brow_ = ((lane >> 4) << 3) + (lane & 7);
    int bchi  = (lane >> 3) & 1;

    float acc[2][16][4];
#pragma unroll
    for (int t = 0; t < 2; t++)
#pragma unroll
        for (int n = 0; n < 16; n++)
#pragma unroll
            for (int j = 0; j < 4; j++) acc[t][n][j] = 0.f;

    const int NKI = DIM_D / BK;  // 32

    // ---- prologue: stages 0,1 ----
#pragma unroll
    for (int s = 0; s < 2; s++) {
        int k0 = s * BK;
#pragma unroll
        for (int i = 0; i < 4; i++)
            cpa(sbA + s * A_STAGE + adst[i], asrc[i] + k0, atok[i] >= 0 ? 16 : 0);
#pragma unroll
        for (int i = 0; i < 8; i++)
            cpa(sbB + s * B_STAGE + bdst[i], bsrc[i] + k0, 16);
        CP_COMMIT();
    }

    int st = 0;
    for (int ks = 0; ks < NKI; ks++) {
        CP_WAIT1();
        __syncthreads();

        // issue stage ks+2
        int kn = ks + 2;
        if (kn < NKI) {
            int sn = st + 2; if (sn >= NSTAGE) sn -= NSTAGE;
            int k0 = kn * BK;
#pragma unroll
            for (int i = 0; i < 4; i++)
                cpa(sbA + sn * A_STAGE + adst[i], asrc[i] + k0, atok[i] >= 0 ? 16 : 0);
#pragma unroll
            for (int i = 0; i < 8; i++)
                cpa(sbB + sn * B_STAGE + bdst[i], bsrc[i] + k0, 16);
        }
        CP_COMMIT();

        // compute stage st
        uint32_t ab = sbA + st * A_STAGE;
        uint32_t bb = sbB + st * B_STAGE;
#pragma unroll
        for (int kb = 0; kb < 4; kb++) {
            uint32_t a[2][4];
#pragma unroll
            for (int tt = 0; tt < 2; tt++)
                ldsm4(a[tt], ab + swz(arow + 16 * tt, 2 * kb + achi));
#pragma unroll
            for (int ntp = 0; ntp < 8; ntp++) {
                uint32_t b[4];
                ldsm4(b, bb + swz(wn + 16 * ntp + brow_, 2 * kb + bchi));
                mma_f16(acc[0][2 * ntp],     a[0], b[0], b[1]);
                mma_f16(acc[0][2 * ntp + 1], a[0], b[2], b[3]);
                mma_f16(acc[1][2 * ntp],     a[1], b[0], b[1]);
                mma_f16(acc[1][2 * ntp + 1], a[1], b[2], b[3]);
            }
        }
        if (++st == NSTAGE) st = 0;
    }

    // ---- epilogue: relu(acc + bias) -> g_operm (fp16) ----
    int g = lane >> 2, q = lane & 3;
    const float* ebrow = eb + (size_t)e * DIM_O;
#pragma unroll
    for (int t = 0; t < 2; t++) {
#pragma unroll
        for (int nt = 0; nt < 16; nt++) {
            int col = n0 + wn + 8 * nt + 2 * q;
            float b0v = ebrow[col], b1v = ebrow[col + 1];
            int r = row0 + wm + 16 * t + g;
            __half2 h0 = __floats2half2_rn(fmaxf(acc[t][nt][0] + b0v, 0.f),
                                           fmaxf(acc[t][nt][1] + b1v, 0.f));
            __half2 h1 = __floats2half2_rn(fmaxf(acc[t][nt][2] + b0v, 0.f),
                                           fmaxf(acc[t][nt][3] + b1v, 0.f));
            *(__half2*)(g_operm + (size_t)r * DIM_O + col) = h0;
            *(__half2*)(g_operm + (size_t)(r + 8) * DIM_O + col) = h1;
        }
    }
}

// ---------------- combine: out[t] = 0.5*(row_e1 + row_e2) ----------------
__global__ void combine_k(float* __restrict__ out) {
    int t = blockIdx.x;
    const uint4* a = (const uint4*)(g_operm + (size_t)g_pos[2 * t] * DIM_O);
    const uint4* b = (const uint4*)(g_operm + (size_t)g_pos[2 * t + 1] * DIM_O);
    float4* o = (float4*)(out + (size_t)t * DIM_O);
    int i = threadIdx.x;   // 256 threads x 8 halves = 2048
    union { uint4 u; __half2 h[4]; } va, vb;
    va.u = a[i]; vb.u = b[i];
#pragma unroll
    for (int j = 0; j < 4; j += 2) {
        float2 a0 = __half22float2(va.h[j]),     b0 = __half22float2(vb.h[j]);
        float2 a1 = __half22float2(va.h[j + 1]), b1 = __half22float2(vb.h[j + 1]);
        float4 v;
        v.x = 0.5f * (a0.x + b0.x); v.y = 0.5f * (a0.y + b0.y);
        v.z = 0.5f * (a1.x + b1.x); v.w = 0.5f * (a1.y + b1.y);
        o[2 * i + j / 2] = v;
    }
}

// ---------------- host ----------------
extern "C" void kernel_launch(void* const* d_in, const int* in_sizes, int n_in,
                              void* d_out, int out_size) {
    const float* x  = (const float*)d_in[0];
    const float* gw = (const float*)d_in[1];
    const float* gb = (const float*)d_in[2];
    const float* ew = (const float*)d_in[3];
    const float* eb = (const float*)d_in[4];
    float* out = (float*)d_out;

    cudaFuncSetAttribute(moe_hmma, cudaFuncAttributeMaxDynamicSharedMemorySize, SMEM_TOTAL);

    init_k<<<1, 32>>>();                                         // 1
    prep_k<<<GATE_BLKS + WT_BLKS, 256>>>(x, gw, gb, ew);         // 2 (gate || wt)
    scan_k<<<1, 1>>>();                                          // 3
    scatter_k<<<(T_TOKENS * 2) / 256, 256>>>();                  // 4
    moe_hmma<<<dim3(DIM_O / BN, MAX_TILES), 256, SMEM_TOTAL>>>(eb);  // 5
    combine_k<<<T_TOKENS, 256>>>(out);                           // 6
}